// round 1
// baseline (speedup 1.0000x reference)
#include <cuda_runtime.h>
#include <cstdint>
#include <cstddef>

#define T_STEPS 512
#define BATCH   64
#define DIMD    512
#define DIMH    512
#define N4H     2048   // 4 gates * H, packed as j' = hid*4 + gate
#define KDIM    512

// ---------------- device scratch (static: no runtime allocation) ----------------
__device__ float g_Wx[DIMD * N4H];                       // 4 MB  [k][j']
__device__ float g_Wh[DIMH * N4H];                       // 4 MB  [k][j']
__device__ float g_bias[N4H];
__device__ float g_Xproj[(size_t)T_STEPS * BATCH * N4H]; // 256 MB [t*B+b][j']  (x@Wx + b)
__device__ float g_hbuf[2][BATCH * DIMH];                // ping-pong h
__device__ unsigned g_count;
__device__ volatile unsigned g_phase;

// ---------------- f32x2 helpers (FFMA2: PTX-only, 2x fp32 FMA rate) -------------
struct __align__(16) ULL2 { unsigned long long x, y; };

static __device__ __forceinline__ unsigned long long pack2(float v) {
    unsigned long long r;
    unsigned u = __float_as_uint(v);
    asm("mov.b64 %0, {%1, %2};" : "=l"(r) : "r"(u), "r"(u));
    return r;
}
static __device__ __forceinline__ unsigned long long fma2(unsigned long long a,
                                                          unsigned long long b,
                                                          unsigned long long c) {
    unsigned long long d;
    asm("fma.rn.f32x2 %0, %1, %2, %3;" : "=l"(d) : "l"(a), "l"(b), "l"(c));
    return d;
}
static __device__ __forceinline__ float lo32(unsigned long long v) {
    return __uint_as_float((unsigned)(v & 0xffffffffull));
}
static __device__ __forceinline__ float hi32(unsigned long long v) {
    return __uint_as_float((unsigned)(v >> 32));
}
static __device__ __forceinline__ float sigf(float x) { return 1.0f / (1.0f + expf(-x)); }

// ---------------- kernel 1: pack weights, reset barrier, zero h -----------------
__global__ void pack_kernel(const float* __restrict__ Wf, const float* __restrict__ bf,
                            const float* __restrict__ Wi, const float* __restrict__ bi,
                            const float* __restrict__ Wg, const float* __restrict__ bg,
                            const float* __restrict__ Wo, const float* __restrict__ bo) {
    int idx = blockIdx.x * blockDim.x + threadIdx.x;
    int stride = gridDim.x * blockDim.x;
    if (idx == 0) { g_count = 0; g_phase = 0; }
    for (int i = idx; i < DIMD * N4H; i += stride) {
        int k = i >> 11;          // / 2048
        int j = i & 2047;         // j' = c*4 + g
        int g = j & 3;
        int c = j >> 2;
        const float* W = (g == 0) ? Wf : (g == 1) ? Wi : (g == 2) ? Wg : Wo;
        g_Wx[i] = W[(size_t)k * DIMH + c];
        g_Wh[i] = W[(size_t)(DIMD + k) * DIMH + c];
    }
    for (int i = idx; i < N4H; i += stride) {
        int g = i & 3, c = i >> 2;
        const float* B = (g == 0) ? bf : (g == 1) ? bi : (g == 2) ? bg : bo;
        g_bias[i] = B[c];
    }
    for (int i = idx; i < 2 * BATCH * DIMH; i += stride)
        ((float*)g_hbuf)[i] = 0.0f;
}

// ---------------- kernel 2: X-projection GEMM  [T*B,512] @ [512,2048] + bias ----
// BM=128, BN=64, BK=16, 256 threads, 8x4 microtile per thread, f32x2 FMAs.
__global__ __launch_bounds__(256) void xproj_gemm(const float* __restrict__ A) {
    __shared__ float As[16 * 132];   // [k][m] transposed, pad 132 (16B-aligned rows)
    __shared__ float Bs[16 * 64];    // [k][n]

    const int tid = threadIdx.x;
    const int tx = tid & 15;         // 0..15 -> 4 cols
    const int ty = tid >> 4;         // 0..15 -> 8 rows
    const int m0 = blockIdx.y * 128;
    const int n0 = blockIdx.x * 64;

    unsigned long long acc[8][2];
#pragma unroll
    for (int r = 0; r < 8; ++r) { acc[r][0] = 0ull; acc[r][1] = 0ull; }

    const int arow = tid >> 1;           // 0..127
    const int acol = (tid & 1) * 8;      // 0 or 8
    const int brow = tid >> 4;           // 0..15
    const int bcol = (tid & 15) * 4;     // 0..60

    for (int k0 = 0; k0 < KDIM; k0 += 16) {
        float4 av0 = *(const float4*)&A[(size_t)(m0 + arow) * DIMD + k0 + acol];
        float4 av1 = *(const float4*)&A[(size_t)(m0 + arow) * DIMD + k0 + acol + 4];
        float4 bv  = *(const float4*)&g_Wx[(size_t)(k0 + brow) * N4H + n0 + bcol];
        __syncthreads();   // previous iter's reads done before overwrite
        As[(acol + 0) * 132 + arow] = av0.x;
        As[(acol + 1) * 132 + arow] = av0.y;
        As[(acol + 2) * 132 + arow] = av0.z;
        As[(acol + 3) * 132 + arow] = av0.w;
        As[(acol + 4) * 132 + arow] = av1.x;
        As[(acol + 5) * 132 + arow] = av1.y;
        As[(acol + 6) * 132 + arow] = av1.z;
        As[(acol + 7) * 132 + arow] = av1.w;
        *(float4*)&Bs[brow * 64 + bcol] = bv;
        __syncthreads();

#pragma unroll
        for (int kk = 0; kk < 16; ++kk) {
            float4 a0 = *(const float4*)&As[kk * 132 + ty * 8];
            float4 a1 = *(const float4*)&As[kk * 132 + ty * 8 + 4];
            ULL2 b2 = *(const ULL2*)&Bs[kk * 64 + tx * 4];
            float ar[8] = {a0.x, a0.y, a0.z, a0.w, a1.x, a1.y, a1.z, a1.w};
#pragma unroll
            for (int r = 0; r < 8; ++r) {
                unsigned long long pa = pack2(ar[r]);
                acc[r][0] = fma2(pa, b2.x, acc[r][0]);
                acc[r][1] = fma2(pa, b2.y, acc[r][1]);
            }
        }
    }

    float4 bias = *(const float4*)&g_bias[n0 + tx * 4];
#pragma unroll
    for (int r = 0; r < 8; ++r) {
        float4 o;
        o.x = lo32(acc[r][0]) + bias.x;
        o.y = hi32(acc[r][0]) + bias.y;
        o.z = lo32(acc[r][1]) + bias.z;
        o.w = hi32(acc[r][1]) + bias.w;
        *(float4*)&g_Xproj[(size_t)(m0 + ty * 8 + r) * N4H + n0 + tx * 4] = o;
    }
}

// ---------------- kernel 3: persistent recurrence --------------------------------
// 128 CTAs x 128 threads. CTA r owns hidden units [r*4, r*4+4) -> gate cols
// [r*16, r*16+16). Thread (cp = t/32, lane = t%32): hidden = r*4+cp,
// batches b0 = 2*lane, b0+1. c kept in registers. One grid barrier per step.
#define REC_SMEM_FLOATS (DIMH * 16 + 2 * 64 * 66)

__global__ __launch_bounds__(128, 1) void lstm_kernel(float* __restrict__ out, int out_size) {
    extern __shared__ float smem[];
    float* Whs = smem;                  // [512][16]
    float* hsb = smem + DIMH * 16;      // [2][64][66]  hs[buf][k_local][b]

    const int r    = blockIdx.x;
    const int t    = threadIdx.x;
    const int cp   = t >> 5;            // 0..3
    const int lane = t & 31;
    const int b0   = lane * 2;
    const int hid  = r * 4 + cp;
    const int jbase = r * 16 + cp * 4;  // = hid*4

    // load Wh slice once
    for (int i = t; i < DIMH * 16; i += 128) {
        int k = i >> 4, c = i & 15;
        Whs[k * 16 + c] = g_Wh[(size_t)k * N4H + r * 16 + c];
    }
    __syncthreads();

    const int ldb = t >> 1;             // batch row staged by this thread
    const int ldk = (t & 1) * 32;       // k-offset within 64-chunk

    float c0 = 0.0f, c1 = 0.0f;
    const size_t tail = (size_t)T_STEPS * BATCH * DIMH;
    const bool write_state = (size_t)out_size >= tail + 2u * BATCH * DIMH;

    for (int step = 0; step < T_STEPS; ++step) {
        const int cur = step & 1;
        const float* __restrict__ hsrc = g_hbuf[cur];

        // x-projection for this step (includes bias)
        const float* xpr = &g_Xproj[((size_t)step * BATCH) * N4H + jbase];
        float4 xp0 = *(const float4*)&xpr[(size_t)b0 * N4H];
        float4 xp1 = *(const float4*)&xpr[(size_t)(b0 + 1) * N4H];

        unsigned long long a00 = 0, a01 = 0, a10 = 0, a11 = 0;

        // prefetch chunk 0 (L2-only loads: h lines are rewritten every 2 steps)
        float4 stg[8];
#pragma unroll
        for (int q = 0; q < 8; ++q)
            stg[q] = __ldcg((const float4*)&hsrc[ldb * DIMH + ldk + q * 4]);

        for (int ci = 0; ci < 8; ++ci) {
            float* hb = hsb + (ci & 1) * (64 * 66);
#pragma unroll
            for (int q = 0; q < 8; ++q) {
                float4 v = stg[q];
                hb[(ldk + q * 4 + 0) * 66 + ldb] = v.x;
                hb[(ldk + q * 4 + 1) * 66 + ldb] = v.y;
                hb[(ldk + q * 4 + 2) * 66 + ldb] = v.z;
                hb[(ldk + q * 4 + 3) * 66 + ldb] = v.w;
            }
            __syncthreads();
            if (ci < 7) {
                const float* src = &hsrc[ldb * DIMH + (ci + 1) * 64 + ldk];
#pragma unroll
                for (int q = 0; q < 8; ++q)
                    stg[q] = __ldcg((const float4*)&src[q * 4]);
            }
#pragma unroll 8
            for (int kk = 0; kk < 64; ++kk) {
                float2 hv = *(const float2*)&hb[kk * 66 + b0];
                ULL2 wv = *(const ULL2*)&Whs[(ci * 64 + kk) * 16 + cp * 4];
                unsigned long long p0 = pack2(hv.x);
                unsigned long long p1 = pack2(hv.y);
                a00 = fma2(p0, wv.x, a00);
                a01 = fma2(p0, wv.y, a01);
                a10 = fma2(p1, wv.x, a10);
                a11 = fma2(p1, wv.y, a11);
            }
        }

        // cell update (gate order within j' group: f,i,g,o)
        float zf0 = lo32(a00) + xp0.x, zi0 = hi32(a00) + xp0.y;
        float zg0 = lo32(a01) + xp0.z, zo0 = hi32(a01) + xp0.w;
        float zf1 = lo32(a10) + xp1.x, zi1 = hi32(a10) + xp1.y;
        float zg1 = lo32(a11) + xp1.z, zo1 = hi32(a11) + xp1.w;

        c0 = sigf(zf0) * c0 + sigf(zi0) * tanhf(zg0);
        c1 = sigf(zf1) * c1 + sigf(zi1) * tanhf(zg1);
        float h0 = sigf(zo0) * tanhf(c0);
        float h1 = sigf(zo1) * tanhf(c1);

        const int nxt = cur ^ 1;
        g_hbuf[nxt][b0 * DIMH + hid]       = h0;
        g_hbuf[nxt][(b0 + 1) * DIMH + hid] = h1;
        size_t obase = ((size_t)step * BATCH + b0) * DIMH + hid;
        out[obase]        = h0;
        out[obase + DIMH] = h1;
        if (step == T_STEPS - 1 && write_state) {
            out[tail + (size_t)b0 * DIMH + hid]       = h0;
            out[tail + (size_t)(b0 + 1) * DIMH + hid] = h1;
            out[tail + (size_t)BATCH * DIMH + (size_t)b0 * DIMH + hid]       = c0;
            out[tail + (size_t)BATCH * DIMH + (size_t)(b0 + 1) * DIMH + hid] = c1;
        }

        // ---- grid barrier ----
        __threadfence();
        __syncthreads();
        if (t == 0) {
            unsigned arrived = atomicAdd(&g_count, 1u);
            if (arrived == (unsigned)gridDim.x - 1u) {
                g_count = 0;
                __threadfence();
                g_phase = (unsigned)(step + 1);
            } else {
                while (g_phase < (unsigned)(step + 1)) { }
                __threadfence();
            }
        }
        __syncthreads();
    }
}

// ---------------- launch ----------------------------------------------------------
extern "C" void kernel_launch(void* const* d_in, const int* in_sizes, int n_in,
                              void* d_out, int out_size) {
    const float* inputs = (const float*)d_in[0];
    const float* Wf = (const float*)d_in[1];
    const float* bf = (const float*)d_in[2];
    const float* Wi = (const float*)d_in[3];
    const float* bi = (const float*)d_in[4];
    const float* Wg = (const float*)d_in[5];
    const float* bg = (const float*)d_in[6];
    const float* Wo = (const float*)d_in[7];
    const float* bo = (const float*)d_in[8];

    pack_kernel<<<512, 256>>>(Wf, bf, Wi, bi, Wg, bg, Wo, bo);

    dim3 g1(N4H / 64, (T_STEPS * BATCH) / 128);   // (32, 256)
    xproj_gemm<<<g1, 256>>>(inputs);

    const int rec_smem = REC_SMEM_FLOATS * (int)sizeof(float);   // 66560 B
    cudaFuncSetAttribute(lstm_kernel, cudaFuncAttributeMaxDynamicSharedMemorySize, rec_smem);
    lstm_kernel<<<128, 128, rec_smem>>>((float*)d_out, out_size);
}

// round 2
// speedup vs baseline: 1.5348x; 1.5348x over previous
#include <cuda_runtime.h>
#include <cstdint>
#include <cstddef>

#define T_STEPS 512
#define BATCH   64
#define DIMD    512
#define DIMH    512
#define N4H     2048   // 4 gates * H, packed as j' = hid*4 + gate
#define KDIM    512

// ---------------- device scratch (static: no runtime allocation) ----------------
__device__ float g_Wx[DIMD * N4H];                       // 4 MB  [k][j']
__device__ float g_Wh[DIMH * N4H];                       // 4 MB  [k][j']
__device__ float g_bias[N4H];
__device__ float g_Xproj[(size_t)T_STEPS * BATCH * N4H]; // 256 MB [t*B+b][j']  (x@Wx + b)
__device__ float g_hbuf[2][BATCH * DIMH];                // ping-pong h
__device__ unsigned g_count;
__device__ volatile unsigned g_phase;

// ---------------- f32x2 helpers (FFMA2: PTX-only, 2x fp32 FMA rate) -------------
struct __align__(16) ULL2 { unsigned long long x, y; };

static __device__ __forceinline__ unsigned long long pack2(float v) {
    unsigned long long r;
    unsigned u = __float_as_uint(v);
    asm("mov.b64 %0, {%1, %2};" : "=l"(r) : "r"(u), "r"(u));
    return r;
}
static __device__ __forceinline__ unsigned long long fma2(unsigned long long a,
                                                          unsigned long long b,
                                                          unsigned long long c) {
    unsigned long long d;
    asm("fma.rn.f32x2 %0, %1, %2, %3;" : "=l"(d) : "l"(a), "l"(b), "l"(c));
    return d;
}
static __device__ __forceinline__ unsigned long long add2(unsigned long long a,
                                                          unsigned long long b) {
    unsigned long long d;
    asm("add.rn.f32x2 %0, %1, %2;" : "=l"(d) : "l"(a), "l"(b));
    return d;
}
static __device__ __forceinline__ float lo32(unsigned long long v) {
    return __uint_as_float((unsigned)(v & 0xffffffffull));
}
static __device__ __forceinline__ float hi32(unsigned long long v) {
    return __uint_as_float((unsigned)(v >> 32));
}
static __device__ __forceinline__ float sigf(float x) {
    return __fdividef(1.0f, 1.0f + __expf(-x));
}
static __device__ __forceinline__ float tanh_(float x) {
    return 2.0f * sigf(2.0f * x) - 1.0f;
}

// ---------------- kernel 1: pack weights, reset barrier, zero h -----------------
__global__ void pack_kernel(const float* __restrict__ Wf, const float* __restrict__ bf,
                            const float* __restrict__ Wi, const float* __restrict__ bi,
                            const float* __restrict__ Wg, const float* __restrict__ bg,
                            const float* __restrict__ Wo, const float* __restrict__ bo) {
    int idx = blockIdx.x * blockDim.x + threadIdx.x;
    int stride = gridDim.x * blockDim.x;
    if (idx == 0) { g_count = 0; g_phase = 0; }
    for (int i = idx; i < DIMD * N4H; i += stride) {
        int k = i >> 11;          // / 2048
        int j = i & 2047;         // j' = c*4 + g
        int g = j & 3;
        int c = j >> 2;
        const float* W = (g == 0) ? Wf : (g == 1) ? Wi : (g == 2) ? Wg : Wo;
        g_Wx[i] = W[(size_t)k * DIMH + c];
        g_Wh[i] = W[(size_t)(DIMD + k) * DIMH + c];
    }
    for (int i = idx; i < N4H; i += stride) {
        int g = i & 3, c = i >> 2;
        const float* B = (g == 0) ? bf : (g == 1) ? bi : (g == 2) ? bg : bo;
        g_bias[i] = B[c];
    }
    for (int i = idx; i < 2 * BATCH * DIMH; i += stride)
        ((float*)g_hbuf)[i] = 0.0f;
}

// ---------------- kernel 2: X-projection GEMM  [T*B,512] @ [512,2048] + bias ----
// BM=128, BN=64, BK=16, 256 threads, 8x4 microtile per thread, f32x2 FMAs.
__global__ __launch_bounds__(256) void xproj_gemm(const float* __restrict__ A) {
    __shared__ float As[16 * 132];   // [k][m] transposed, pad 132 (16B-aligned rows)
    __shared__ float Bs[16 * 64];    // [k][n]

    const int tid = threadIdx.x;
    const int tx = tid & 15;         // 0..15 -> 4 cols
    const int ty = tid >> 4;         // 0..15 -> 8 rows
    const int m0 = blockIdx.y * 128;
    const int n0 = blockIdx.x * 64;

    unsigned long long acc[8][2];
#pragma unroll
    for (int r = 0; r < 8; ++r) { acc[r][0] = 0ull; acc[r][1] = 0ull; }

    const int arow = tid >> 1;           // 0..127
    const int acol = (tid & 1) * 8;      // 0 or 8
    const int brow = tid >> 4;           // 0..15
    const int bcol = (tid & 15) * 4;     // 0..60

    for (int k0 = 0; k0 < KDIM; k0 += 16) {
        float4 av0 = *(const float4*)&A[(size_t)(m0 + arow) * DIMD + k0 + acol];
        float4 av1 = *(const float4*)&A[(size_t)(m0 + arow) * DIMD + k0 + acol + 4];
        float4 bv  = *(const float4*)&g_Wx[(size_t)(k0 + brow) * N4H + n0 + bcol];
        __syncthreads();   // previous iter's reads done before overwrite
        As[(acol + 0) * 132 + arow] = av0.x;
        As[(acol + 1) * 132 + arow] = av0.y;
        As[(acol + 2) * 132 + arow] = av0.z;
        As[(acol + 3) * 132 + arow] = av0.w;
        As[(acol + 4) * 132 + arow] = av1.x;
        As[(acol + 5) * 132 + arow] = av1.y;
        As[(acol + 6) * 132 + arow] = av1.z;
        As[(acol + 7) * 132 + arow] = av1.w;
        *(float4*)&Bs[brow * 64 + bcol] = bv;
        __syncthreads();

#pragma unroll
        for (int kk = 0; kk < 16; ++kk) {
            float4 a0 = *(const float4*)&As[kk * 132 + ty * 8];
            float4 a1 = *(const float4*)&As[kk * 132 + ty * 8 + 4];
            ULL2 b2 = *(const ULL2*)&Bs[kk * 64 + tx * 4];
            float ar[8] = {a0.x, a0.y, a0.z, a0.w, a1.x, a1.y, a1.z, a1.w};
#pragma unroll
            for (int r = 0; r < 8; ++r) {
                unsigned long long pa = pack2(ar[r]);
                acc[r][0] = fma2(pa, b2.x, acc[r][0]);
                acc[r][1] = fma2(pa, b2.y, acc[r][1]);
            }
        }
    }

    float4 bias = *(const float4*)&g_bias[n0 + tx * 4];
#pragma unroll
    for (int r = 0; r < 8; ++r) {
        float4 o;
        o.x = lo32(acc[r][0]) + bias.x;
        o.y = hi32(acc[r][0]) + bias.y;
        o.z = lo32(acc[r][1]) + bias.z;
        o.w = hi32(acc[r][1]) + bias.w;
        *(float4*)&g_Xproj[(size_t)(m0 + ty * 8 + r) * N4H + n0 + tx * 4] = o;
    }
}

// ---------------- kernel 3: persistent recurrence (v2) ---------------------------
// 128 CTAs x 256 threads (8 warps = 2/SMSP).
// CTA r owns hidden units [r*4, r*4+4) -> packed gate cols [r*16, r*16+16).
// Warp w owns k-slice [w*64, w*64+64). Thread (w, lane): batches lane, lane+32,
// ALL 16 cols, its warp's 64 k. h read straight from L2 (__ldcg) — each h element
// touched by exactly one thread per CTA, so NO smem staging and NO per-chunk syncs.
// k-partials combined once per step via padded smem exchange; activations on
// warps 0-3 (unit u = w), one warp per SMSP.
//
// smem: Whs [512][16] = 32KB ; comb ULL[8][32][17] (pad 17 -> conflict-free) = 34KB.
#define REC_SMEM_BYTES (DIMH * 16 * 4 + 8 * 32 * 17 * 8)

__global__ __launch_bounds__(256, 1) void lstm_kernel(float* __restrict__ out, int out_size) {
    extern __shared__ float smem[];
    float* Whs = smem;                                          // [512][16]
    unsigned long long* comb = (unsigned long long*)(smem + DIMH * 16); // [8][32][17]

    const int r    = blockIdx.x;
    const int t    = threadIdx.x;
    const int w    = t >> 5;            // 0..7 : k-slice owner
    const int lane = t & 31;            // batch b0 = lane, b1 = lane+32

    // load Wh slice once: Whs[k][c] = g_Wh[k][r*16 + c]
    for (int i = t; i < DIMH * 16; i += 256) {
        int k = i >> 4, c = i & 15;
        Whs[i] = g_Wh[(size_t)k * N4H + r * 16 + c];
    }
    __syncthreads();

    float c0 = 0.0f, c1 = 0.0f;
    const size_t tail = (size_t)T_STEPS * BATCH * DIMH;
    const bool write_state = (size_t)out_size >= tail + 2u * BATCH * DIMH;

    for (int step = 0; step < T_STEPS; ++step) {
        const int cur = step & 1;
        const float* __restrict__ hsrc = g_hbuf[cur];

        // x-projection (DRAM) — issue early for warps 0-3 (the activation warps)
        float4 xpA, xpB;
        if (w < 4) {
            const float* xb = g_Xproj + ((size_t)step * BATCH + lane) * N4H + r * 16 + w * 4;
            xpA = *(const float4*)xb;
            xpB = *(const float4*)(xb + (size_t)32 * N4H);
        }

        const float* __restrict__ hrow0 = hsrc + (size_t)lane * DIMH + w * 64;
        const float* __restrict__ hrow1 = hsrc + (size_t)(lane + 32) * DIMH + w * 64;

        unsigned long long acc[16];
#pragma unroll
        for (int i = 0; i < 16; ++i) acc[i] = 0ull;

        // depth-2 LDG prefetch pipeline over 16 k-quads
        float4 pf0[2], pf1[2];
        pf0[0] = __ldcg((const float4*)(hrow0));
        pf1[0] = __ldcg((const float4*)(hrow1));
        pf0[1] = __ldcg((const float4*)(hrow0 + 4));
        pf1[1] = __ldcg((const float4*)(hrow1 + 4));

#pragma unroll
        for (int q = 0; q < 16; ++q) {
            float4 h0 = pf0[q & 1];
            float4 h1 = pf1[q & 1];
            if (q < 14) {
                pf0[q & 1] = __ldcg((const float4*)(hrow0 + (q + 2) * 4));
                pf1[q & 1] = __ldcg((const float4*)(hrow1 + (q + 2) * 4));
            }
            const float* wq = &Whs[(w * 64 + q * 4) * 16];
            float ha0[4] = {h0.x, h0.y, h0.z, h0.w};
            float ha1[4] = {h1.x, h1.y, h1.z, h1.w};
#pragma unroll
            for (int j = 0; j < 4; ++j) {
                ULL2 wA = *(const ULL2*)(wq + j * 16);
                ULL2 wB = *(const ULL2*)(wq + j * 16 + 4);
                ULL2 wC = *(const ULL2*)(wq + j * 16 + 8);
                ULL2 wD = *(const ULL2*)(wq + j * 16 + 12);
                unsigned long long p0 = pack2(ha0[j]);
                unsigned long long p1 = pack2(ha1[j]);
                acc[0]  = fma2(p0, wA.x, acc[0]);
                acc[1]  = fma2(p0, wA.y, acc[1]);
                acc[2]  = fma2(p0, wB.x, acc[2]);
                acc[3]  = fma2(p0, wB.y, acc[3]);
                acc[4]  = fma2(p0, wC.x, acc[4]);
                acc[5]  = fma2(p0, wC.y, acc[5]);
                acc[6]  = fma2(p0, wD.x, acc[6]);
                acc[7]  = fma2(p0, wD.y, acc[7]);
                acc[8]  = fma2(p1, wA.x, acc[8]);
                acc[9]  = fma2(p1, wA.y, acc[9]);
                acc[10] = fma2(p1, wB.x, acc[10]);
                acc[11] = fma2(p1, wB.y, acc[11]);
                acc[12] = fma2(p1, wC.x, acc[12]);
                acc[13] = fma2(p1, wC.y, acc[13]);
                acc[14] = fma2(p1, wD.x, acc[14]);
                acc[15] = fma2(p1, wD.y, acc[15]);
            }
        }

        // exchange k-partials: every warp writes its 16 accs (pad 17 -> no conflicts)
        {
            unsigned long long* cw = comb + ((size_t)w * 32 + lane) * 17;
#pragma unroll
            for (int i = 0; i < 16; ++i) cw[i] = acc[i];
        }
        __syncthreads();

        // warps 0-3: unit u = w. Sum the 8 k-partials, apply gates, write h.
        if (w < 4) {
            const int u = w;
            unsigned long long s0 = 0, s1 = 0, s2 = 0, s3 = 0;
#pragma unroll
            for (int kh = 0; kh < 8; ++kh) {
                const unsigned long long* cr = comb + ((size_t)kh * 32 + lane) * 17;
                s0 = add2(s0, cr[u * 2]);         // b0: cols (f,i)
                s1 = add2(s1, cr[u * 2 + 1]);     // b0: cols (g,o)
                s2 = add2(s2, cr[8 + u * 2]);     // b1: (f,i)
                s3 = add2(s3, cr[8 + u * 2 + 1]); // b1: (g,o)
            }
            float zf0 = lo32(s0) + xpA.x, zi0 = hi32(s0) + xpA.y;
            float zg0 = lo32(s1) + xpA.z, zo0 = hi32(s1) + xpA.w;
            float zf1 = lo32(s2) + xpB.x, zi1 = hi32(s2) + xpB.y;
            float zg1 = lo32(s3) + xpB.z, zo1 = hi32(s3) + xpB.w;

            c0 = sigf(zf0) * c0 + sigf(zi0) * tanh_(zg0);
            c1 = sigf(zf1) * c1 + sigf(zi1) * tanh_(zg1);
            float h0v = sigf(zo0) * tanh_(c0);
            float h1v = sigf(zo1) * tanh_(c1);

            const int hid = r * 4 + u;
            const int nxt = cur ^ 1;
            g_hbuf[nxt][lane * DIMH + hid]        = h0v;
            g_hbuf[nxt][(lane + 32) * DIMH + hid] = h1v;
            out[((size_t)step * BATCH + lane) * DIMH + hid]      = h0v;
            out[((size_t)step * BATCH + lane + 32) * DIMH + hid] = h1v;
            if (step == T_STEPS - 1 && write_state) {
                out[tail + (size_t)lane * DIMH + hid]        = h0v;
                out[tail + (size_t)(lane + 32) * DIMH + hid] = h1v;
                out[tail + (size_t)BATCH * DIMH + (size_t)lane * DIMH + hid]        = c0;
                out[tail + (size_t)BATCH * DIMH + (size_t)(lane + 32) * DIMH + hid] = c1;
            }
        }

        // ---- grid barrier ----
        __threadfence();
        __syncthreads();
        if (t == 0) {
            unsigned arrived = atomicAdd(&g_count, 1u);
            if (arrived == (unsigned)gridDim.x - 1u) {
                g_count = 0;
                __threadfence();
                g_phase = (unsigned)(step + 1);
            } else {
                while (g_phase < (unsigned)(step + 1)) { }
                __threadfence();
            }
        }
        __syncthreads();
    }
}

// ---------------- launch ----------------------------------------------------------
extern "C" void kernel_launch(void* const* d_in, const int* in_sizes, int n_in,
                              void* d_out, int out_size) {
    const float* inputs = (const float*)d_in[0];
    const float* Wf = (const float*)d_in[1];
    const float* bf = (const float*)d_in[2];
    const float* Wi = (const float*)d_in[3];
    const float* bi = (const float*)d_in[4];
    const float* Wg = (const float*)d_in[5];
    const float* bg = (const float*)d_in[6];
    const float* Wo = (const float*)d_in[7];
    const float* bo = (const float*)d_in[8];

    pack_kernel<<<512, 256>>>(Wf, bf, Wi, bi, Wg, bg, Wo, bo);

    dim3 g1(N4H / 64, (T_STEPS * BATCH) / 128);   // (32, 256)
    xproj_gemm<<<g1, 256>>>(inputs);

    const int rec_smem = REC_SMEM_BYTES;   // 32768 + 34816 = 67584 B
    cudaFuncSetAttribute(lstm_kernel, cudaFuncAttributeMaxDynamicSharedMemorySize, rec_smem);
    lstm_kernel<<<128, 256, rec_smem>>>((float*)d_out, out_size);
}